// round 2
// baseline (speedup 1.0000x reference)
#include <cuda_runtime.h>
#include <cstdint>

// Problem constants (fixed by the reference)
#define MAXN 100000
#define MAXE 1600000
#define DIN 128
#define DH  128
#define DOUT 64

// Scratch (device globals — no allocation allowed)
__device__ float g_deg [MAXN];
__device__ float g_dinv[MAXN];
__device__ float g_h1  [(size_t)MAXN * DH];    // x @ W1
__device__ float g_agg1[(size_t)MAXN * DH];    // aggregated layer-1
__device__ float g_h2  [(size_t)MAXN * DOUT];  // relu(agg1+b1) @ W2

// ---------------------------------------------------------------------------
// Degree / normalization
// ---------------------------------------------------------------------------
__global__ void k_init_deg(float* deg, int n) {
    int i = blockIdx.x * blockDim.x + threadIdx.x;
    if (i < n) deg[i] = 1.0f;  // self-loop
}

__global__ void k_count_deg(const int* __restrict__ dst, float* deg, int ne) {
    int i = blockIdx.x * blockDim.x + threadIdx.x;
    if (i < ne) atomicAdd(&deg[dst[i]], 1.0f);
}

__global__ void k_dinv(const float* __restrict__ deg, float* dinv, int n) {
    int i = blockIdx.x * blockDim.x + threadIdx.x;
    if (i < n) dinv[i] = rsqrtf(deg[i]);
}

// ---------------------------------------------------------------------------
// Tiled fp32 GEMM: C[M x BN] = A[M x K] @ W[K x BN]
// BM=64, BK=16, blockDim(16,16), each thread computes 4 x TN outputs.
// FUSE: A is read as relu(A + bias[k])  (bias indexed by the K dimension)
// ---------------------------------------------------------------------------
template <int BN, int TN, bool FUSE>
__global__ void k_gemm(const float* __restrict__ A, const float* __restrict__ W,
                       const float* __restrict__ bias, float* __restrict__ C,
                       int M, int K) {
    __shared__ float As[16][65];   // [k][m], padded to kill bank conflicts
    __shared__ float Ws[16][BN];   // [k][n]

    const int m0 = blockIdx.x * 64;
    const int t  = threadIdx.y * 16 + threadIdx.x;

    float acc[4][TN];
#pragma unroll
    for (int i = 0; i < 4; i++)
#pragma unroll
        for (int j = 0; j < TN; j++) acc[i][j] = 0.0f;

    for (int k0 = 0; k0 < K; k0 += 16) {
        // Load A tile 64x16 (1024 elems / 256 threads = 4 each), coalesced in k
#pragma unroll
        for (int i = 0; i < 4; i++) {
            int idx = i * 256 + t;
            int m = idx >> 4;        // 0..63
            int k = idx & 15;        // 0..15
            int gm = m0 + m;
            float v = 0.0f;
            if (gm < M) {
                v = A[(size_t)gm * K + k0 + k];
                if (FUSE) v = fmaxf(v + bias[k0 + k], 0.0f);
            }
            As[k][m] = v;
        }
        // Load W tile 16xBN
#pragma unroll
        for (int i = 0; i < (16 * BN) / 256; i++) {
            int idx = i * 256 + t;
            int k = idx / BN;
            int c = idx % BN;
            Ws[k][c] = W[(size_t)(k0 + k) * BN + c];
        }
        __syncthreads();

#pragma unroll
        for (int kk = 0; kk < 16; kk++) {
            float a[4], w[TN];
#pragma unroll
            for (int i = 0; i < 4; i++) a[i] = As[kk][threadIdx.y * 4 + i];
#pragma unroll
            for (int j = 0; j < TN; j++) w[j] = Ws[kk][threadIdx.x * TN + j];
#pragma unroll
            for (int i = 0; i < 4; i++)
#pragma unroll
                for (int j = 0; j < TN; j++) acc[i][j] += a[i] * w[j];
        }
        __syncthreads();
    }

#pragma unroll
    for (int i = 0; i < 4; i++) {
        int gm = m0 + threadIdx.y * 4 + i;
        if (gm < M) {
#pragma unroll
            for (int j = 0; j < TN; j++)
                C[(size_t)gm * BN + threadIdx.x * TN + j] = acc[i][j];
        }
    }
}

// ---------------------------------------------------------------------------
// Self-loop initialization (avoids a separate zero pass)
// ---------------------------------------------------------------------------
__global__ void k_selfinit128(const float* __restrict__ h, const float* __restrict__ dinv,
                              float* __restrict__ agg, int n) {
    int i = blockIdx.x * blockDim.x + threadIdx.x;  // one float4 per thread
    if (i < n * 32) {
        int node = i >> 5;
        float s = dinv[node];
        s = s * s;
        float4 v = reinterpret_cast<const float4*>(h)[i];
        v.x *= s; v.y *= s; v.z *= s; v.w *= s;
        reinterpret_cast<float4*>(agg)[i] = v;
    }
}

__global__ void k_selfinit64(const float* __restrict__ h, const float* __restrict__ dinv,
                             const float* __restrict__ b, float* __restrict__ out, int n) {
    int i = blockIdx.x * blockDim.x + threadIdx.x;  // one float4 per thread
    if (i < n * 16) {
        int node = i >> 4;
        int c4 = i & 15;
        float s = dinv[node];
        s = s * s;
        float4 v = reinterpret_cast<const float4*>(h)[i];
        float4 bb = reinterpret_cast<const float4*>(b)[c4];
        v.x = v.x * s + bb.x;
        v.y = v.y * s + bb.y;
        v.z = v.z * s + bb.z;
        v.w = v.w * s + bb.w;
        reinterpret_cast<float4*>(out)[i] = v;
    }
}

// ---------------------------------------------------------------------------
// Edge aggregation: agg[dst] += h[src] * dinv[src]*dinv[dst]
// D/4 threads per edge (32 for D=128, 16 for D=64); vectorized red.add.v4.f32
// ---------------------------------------------------------------------------
template <int D>
__global__ void k_edge_agg(const int* __restrict__ src, const int* __restrict__ dst,
                           const float* __restrict__ dinv, const float* __restrict__ h,
                           float* __restrict__ agg, int ne) {
    constexpr int TPE = D / 4;
    int gt = blockIdx.x * blockDim.x + threadIdx.x;
    int e = gt / TPE;
    int lane = gt % TPE;
    bool valid = (e < ne);
    int ee = valid ? e : 0;

    int s = 0, d = 0;
    float w = 0.0f;
    if (lane == 0) {
        s = src[ee];
        d = dst[ee];
        w = dinv[s] * dinv[d];
    }
    s = __shfl_sync(0xffffffffu, s, 0, TPE);
    d = __shfl_sync(0xffffffffu, d, 0, TPE);
    w = __shfl_sync(0xffffffffu, w, 0, TPE);

    float4 v = reinterpret_cast<const float4*>(h + (size_t)s * D)[lane];
    v.x *= w; v.y *= w; v.z *= w; v.w *= w;

    if (valid) {
        float* p = agg + (size_t)d * D + lane * 4;
        asm volatile("red.global.add.v4.f32 [%0], {%1, %2, %3, %4};"
                     :: "l"(p), "f"(v.x), "f"(v.y), "f"(v.z), "f"(v.w)
                     : "memory");
    }
}

// ---------------------------------------------------------------------------
// Launch
// ---------------------------------------------------------------------------
extern "C" void kernel_launch(void* const* d_in, const int* in_sizes, int n_in,
                              void* d_out, int out_size) {
    const float* x  = (const float*)d_in[0];   // [N, 128]
    const int*   ei = (const int*)  d_in[1];   // [2, E]
    const float* W1 = (const float*)d_in[2];   // [128, 128]
    const float* b1 = (const float*)d_in[3];   // [128]
    const float* W2 = (const float*)d_in[4];   // [128, 64]
    const float* b2 = (const float*)d_in[5];   // [64]
    float* out = (float*)d_out;                // [N, 64]

    const int N = in_sizes[0] / DIN;
    const int E = in_sizes[1] / 2;
    const int* src = ei;
    const int* dst = ei + E;

    float *deg, *dinv, *h1, *agg1, *h2;
    cudaGetSymbolAddress((void**)&deg,  g_deg);
    cudaGetSymbolAddress((void**)&dinv, g_dinv);
    cudaGetSymbolAddress((void**)&h1,   g_h1);
    cudaGetSymbolAddress((void**)&agg1, g_agg1);
    cudaGetSymbolAddress((void**)&h2,   g_h2);

    const int T = 256;

    // 1. degrees + normalization
    k_init_deg<<<(N + T - 1) / T, T>>>(deg, N);
    k_count_deg<<<(E + T - 1) / T, T>>>(dst, deg, E);
    k_dinv<<<(N + T - 1) / T, T>>>(deg, dinv, N);

    // 2. h1 = x @ W1
    {
        dim3 blk(16, 16);
        k_gemm<DH, 8, false><<<(N + 63) / 64, blk>>>(x, W1, nullptr, h1, N, DIN);
    }

    // 3. agg1 = self-loop init, then edge scatter-add
    k_selfinit128<<<(N * 32 + T - 1) / T, T>>>(h1, dinv, agg1, N);
    {
        long long threads = (long long)E * 32;
        k_edge_agg<DH><<<(int)((threads + T - 1) / T), T>>>(src, dst, dinv, h1, agg1, E);
    }

    // 4. h2 = relu(agg1 + b1) @ W2   (bias+relu fused into A load)
    {
        dim3 blk(16, 16);
        k_gemm<DOUT, 4, true><<<(N + 63) / 64, blk>>>(agg1, W2, b1, h2, N, DH);
    }

    // 5. out = h2*self_norm + b2, then edge scatter-add
    k_selfinit64<<<(N * 16 + T - 1) / T, T>>>(h2, dinv, b2, out, N);
    {
        long long threads = (long long)E * 16;
        k_edge_agg<DOUT><<<(int)((threads + T - 1) / T), T>>>(src, dst, dinv, h2, out, E);
    }
}

// round 3
// speedup vs baseline: 1.4672x; 1.4672x over previous
#include <cuda_runtime.h>
#include <cuda_fp16.h>
#include <cstdint>

#define MAXN 100000
#define MAXE 1600000
#define DIN 128
#define DH  128
#define DOUT 64

// ---------------- scratch (device globals; no allocation allowed) ----------
__device__ int    g_cnt [MAXN];
__device__ int    g_off [MAXN + 1];
__device__ int    g_cur [MAXN];
__device__ int    g_esrc[MAXE];
__device__ float  g_dinv[MAXN];
__device__ __half g_h1s [(size_t)MAXN * DH];    // (x@W1) * dinv[row], fp16
__device__ float  g_a2  [(size_t)MAXN * DH];    // relu(agg1 + b1), fp32
__device__ __half g_h2s [(size_t)MAXN * DOUT];  // (a2@W2) * dinv[row], fp16

struct alignas(8) H2x2 { __half2 a, b; };

// ---------------------------------------------------------------------------
// CSR build
// ---------------------------------------------------------------------------
__global__ void k_zero(int* c, int n) {
    int i = blockIdx.x * blockDim.x + threadIdx.x;
    if (i < n) c[i] = 0;
}

__global__ void k_hist(const int* __restrict__ dst, int* cnt, int ne) {
    int i = blockIdx.x * blockDim.x + threadIdx.x;
    if (i < ne) atomicAdd(&cnt[dst[i]], 1);
}

// single-block exclusive scan over cnt -> off, cur; off[n] = total
__global__ void k_scan(const int* __restrict__ cnt, int* __restrict__ off,
                       int* __restrict__ cur, int n) {
    __shared__ int sums[1024];
    const int t = threadIdx.x;
    const int chunk = (n + 1023) / 1024;
    const int base = t * chunk;
    int s = 0;
    for (int i = 0; i < chunk; i++) {
        int idx = base + i;
        if (idx < n) s += cnt[idx];
    }
    sums[t] = s;
    __syncthreads();
    for (int d = 1; d < 1024; d <<= 1) {
        int v = (t >= d) ? sums[t - d] : 0;
        __syncthreads();
        sums[t] += v;
        __syncthreads();
    }
    int run = sums[t] - s;  // exclusive prefix for this chunk
    for (int i = 0; i < chunk; i++) {
        int idx = base + i;
        if (idx < n) {
            off[idx] = run;
            cur[idx] = run;
            run += cnt[idx];
        }
    }
    if (t == 1023) off[n] = sums[1023];
}

__global__ void k_dinv(const int* __restrict__ cnt, float* dinv, int n) {
    int i = blockIdx.x * blockDim.x + threadIdx.x;
    if (i < n) dinv[i] = rsqrtf((float)cnt[i] + 1.0f);  // +1 self-loop
}

__global__ void k_scatter(const int* __restrict__ src, const int* __restrict__ dst,
                          int* cur, int* __restrict__ esrc, int ne) {
    int i = blockIdx.x * blockDim.x + threadIdx.x;
    if (i < ne) {
        int pos = atomicAdd(&cur[dst[i]], 1);
        esrc[pos] = src[i];
    }
}

// ---------------------------------------------------------------------------
// GEMM1: h1s[m, 0..127] = fp16( (x @ W1)[m, :] * dinv[m] )
// 128x128 block tile, 256 threads, 8x8 per thread, BK=16
// ---------------------------------------------------------------------------
__global__ __launch_bounds__(256, 2)
void k_gemm1(const float* __restrict__ A, const float* __restrict__ W,
             const float* __restrict__ dinv, __half* __restrict__ C, int M) {
    __shared__ float As[16][132];
    __shared__ float Bs[16][128];
    const int m0 = blockIdx.x * 128;
    const int tx = threadIdx.x, ty = threadIdx.y;
    const int t = ty * 16 + tx;

    float acc[8][8];
#pragma unroll
    for (int i = 0; i < 8; i++)
#pragma unroll
        for (int j = 0; j < 8; j++) acc[i][j] = 0.0f;

    for (int k0 = 0; k0 < 128; k0 += 16) {
        // A tile: 128x16 = 512 float4, 2 per thread
#pragma unroll
        for (int i = 0; i < 2; i++) {
            int idx = i * 256 + t;
            int m = idx >> 2, k4 = idx & 3;
            int gm = m0 + m;
            float4 v = make_float4(0.f, 0.f, 0.f, 0.f);
            if (gm < M) v = *(const float4*)(A + (size_t)gm * 128 + k0 + k4 * 4);
            As[k4 * 4 + 0][m] = v.x;
            As[k4 * 4 + 1][m] = v.y;
            As[k4 * 4 + 2][m] = v.z;
            As[k4 * 4 + 3][m] = v.w;
        }
        // B tile: 16x128 = 512 float4, 2 per thread
#pragma unroll
        for (int i = 0; i < 2; i++) {
            int idx = i * 256 + t;
            int k = idx >> 5, c4 = idx & 31;
            *(float4*)&Bs[k][c4 * 4] = *(const float4*)(W + (size_t)(k0 + k) * 128 + c4 * 4);
        }
        __syncthreads();
#pragma unroll
        for (int kk = 0; kk < 16; kk++) {
            float a[8], b[8];
            *(float4*)&a[0] = *(float4*)&As[kk][ty * 8];
            *(float4*)&a[4] = *(float4*)&As[kk][ty * 8 + 4];
            *(float4*)&b[0] = *(float4*)&Bs[kk][tx * 8];
            *(float4*)&b[4] = *(float4*)&Bs[kk][tx * 8 + 4];
#pragma unroll
            for (int i = 0; i < 8; i++)
#pragma unroll
                for (int j = 0; j < 8; j++) acc[i][j] += a[i] * b[j];
        }
        __syncthreads();
    }

#pragma unroll
    for (int i = 0; i < 8; i++) {
        int gm = m0 + ty * 8 + i;
        if (gm < M) {
            float s = dinv[gm];
            __half2* p = (__half2*)(C + (size_t)gm * 128 + tx * 8);
#pragma unroll
            for (int j = 0; j < 4; j++)
                p[j] = __floats2half2_rn(acc[i][2 * j] * s, acc[i][2 * j + 1] * s);
        }
    }
}

// ---------------------------------------------------------------------------
// GEMM2: h2s[m, 0..63] = fp16( (a2 @ W2)[m, :] * dinv[m] )
// 128x64 block tile, 256 threads, 8x4 per thread, BK=16
// ---------------------------------------------------------------------------
__global__ __launch_bounds__(256, 2)
void k_gemm2(const float* __restrict__ A, const float* __restrict__ W,
             const float* __restrict__ dinv, __half* __restrict__ C, int M) {
    __shared__ float As[16][132];
    __shared__ float Bs[16][64];
    const int m0 = blockIdx.x * 128;
    const int tx = threadIdx.x, ty = threadIdx.y;
    const int t = ty * 16 + tx;

    float acc[8][4];
#pragma unroll
    for (int i = 0; i < 8; i++)
#pragma unroll
        for (int j = 0; j < 4; j++) acc[i][j] = 0.0f;

    for (int k0 = 0; k0 < 128; k0 += 16) {
#pragma unroll
        for (int i = 0; i < 2; i++) {
            int idx = i * 256 + t;
            int m = idx >> 2, k4 = idx & 3;
            int gm = m0 + m;
            float4 v = make_float4(0.f, 0.f, 0.f, 0.f);
            if (gm < M) v = *(const float4*)(A + (size_t)gm * 128 + k0 + k4 * 4);
            As[k4 * 4 + 0][m] = v.x;
            As[k4 * 4 + 1][m] = v.y;
            As[k4 * 4 + 2][m] = v.z;
            As[k4 * 4 + 3][m] = v.w;
        }
        // B tile: 16x64 = 256 float4, 1 per thread
        {
            int k = t >> 4, c4 = t & 15;
            *(float4*)&Bs[k][c4 * 4] = *(const float4*)(W + (size_t)(k0 + k) * 64 + c4 * 4);
        }
        __syncthreads();
#pragma unroll
        for (int kk = 0; kk < 16; kk++) {
            float a[8], b[4];
            *(float4*)&a[0] = *(float4*)&As[kk][ty * 8];
            *(float4*)&a[4] = *(float4*)&As[kk][ty * 8 + 4];
            *(float4*)&b[0] = *(float4*)&Bs[kk][tx * 4];
#pragma unroll
            for (int i = 0; i < 8; i++)
#pragma unroll
                for (int j = 0; j < 4; j++) acc[i][j] += a[i] * b[j];
        }
        __syncthreads();
    }

#pragma unroll
    for (int i = 0; i < 8; i++) {
        int gm = m0 + ty * 8 + i;
        if (gm < M) {
            float s = dinv[gm];
            __half2* p = (__half2*)(C + (size_t)gm * 64 + tx * 4);
            p[0] = __floats2half2_rn(acc[i][0] * s, acc[i][1] * s);
            p[1] = __floats2half2_rn(acc[i][2] * s, acc[i][3] * s);
        }
    }
}

// ---------------------------------------------------------------------------
// Aggregation layer 1: one warp per node, D=128.
// a2[n] = relu( dinv[n] * (sum_{src in CSR[n]} h1s[src] + h1s[n]) + b1 )
// ---------------------------------------------------------------------------
__global__ void k_agg1(const int* __restrict__ off, const int* __restrict__ esrc,
                       const float* __restrict__ dinv, const __half* __restrict__ h1s,
                       const float* __restrict__ b1, float* __restrict__ a2, int n) {
    int node = (blockIdx.x * blockDim.x + threadIdx.x) >> 5;
    int lane = threadIdx.x & 31;
    if (node >= n) return;

    const H2x2* rows = (const H2x2*)h1s;  // 32 H2x2 per row (128 halves)

    // self term (h1s is pre-scaled by dinv[src], so self is just own row)
    H2x2 r = rows[(size_t)node * 32 + lane];
    float2 f0 = __half22float2(r.a), f1 = __half22float2(r.b);
    float4 acc = make_float4(f0.x, f0.y, f1.x, f1.y);

    int e = off[node];
    const int end = off[node + 1];
    for (; e + 1 < end; e += 2) {
        int s0 = esrc[e], s1 = esrc[e + 1];
        H2x2 r0 = rows[(size_t)s0 * 32 + lane];
        H2x2 r1 = rows[(size_t)s1 * 32 + lane];
        float2 a0 = __half22float2(r0.a), a1 = __half22float2(r0.b);
        float2 b0 = __half22float2(r1.a), b1v = __half22float2(r1.b);
        acc.x += a0.x + b0.x;
        acc.y += a0.y + b0.y;
        acc.z += a1.x + b1v.x;
        acc.w += a1.y + b1v.y;
    }
    if (e < end) {
        H2x2 r0 = rows[(size_t)esrc[e] * 32 + lane];
        float2 a0 = __half22float2(r0.a), a1 = __half22float2(r0.b);
        acc.x += a0.x;
        acc.y += a0.y;
        acc.z += a1.x;
        acc.w += a1.y;
    }

    float w = dinv[node];
    float4 bb = ((const float4*)b1)[lane];
    float4 o;
    o.x = fmaxf(acc.x * w + bb.x, 0.0f);
    o.y = fmaxf(acc.y * w + bb.y, 0.0f);
    o.z = fmaxf(acc.z * w + bb.z, 0.0f);
    o.w = fmaxf(acc.w * w + bb.w, 0.0f);
    ((float4*)a2)[(size_t)node * 32 + lane] = o;
}

// ---------------------------------------------------------------------------
// Aggregation layer 2: one warp per node, D=64. out = dinv*(sum+self) + b2
// ---------------------------------------------------------------------------
__global__ void k_agg2(const int* __restrict__ off, const int* __restrict__ esrc,
                       const float* __restrict__ dinv, const __half* __restrict__ h2s,
                       const float* __restrict__ b2, float* __restrict__ out, int n) {
    int node = (blockIdx.x * blockDim.x + threadIdx.x) >> 5;
    int lane = threadIdx.x & 31;
    if (node >= n) return;

    const __half2* rows = (const __half2*)h2s;  // 32 half2 per row (64 halves)

    float2 acc = __half22float2(rows[(size_t)node * 32 + lane]);  // self

    int e = off[node];
    const int end = off[node + 1];
    for (; e + 1 < end; e += 2) {
        int s0 = esrc[e], s1 = esrc[e + 1];
        float2 a = __half22float2(rows[(size_t)s0 * 32 + lane]);
        float2 b = __half22float2(rows[(size_t)s1 * 32 + lane]);
        acc.x += a.x + b.x;
        acc.y += a.y + b.y;
    }
    if (e < end) {
        float2 a = __half22float2(rows[(size_t)esrc[e] * 32 + lane]);
        acc.x += a.x;
        acc.y += a.y;
    }

    float w = dinv[node];
    float2 bb = ((const float2*)b2)[lane];
    float2 o;
    o.x = acc.x * w + bb.x;
    o.y = acc.y * w + bb.y;
    ((float2*)out)[(size_t)node * 32 + lane] = o;
}

// ---------------------------------------------------------------------------
// Launch
// ---------------------------------------------------------------------------
extern "C" void kernel_launch(void* const* d_in, const int* in_sizes, int n_in,
                              void* d_out, int out_size) {
    const float* x  = (const float*)d_in[0];   // [N, 128]
    const int*   ei = (const int*)  d_in[1];   // [2, E]
    const float* W1 = (const float*)d_in[2];   // [128, 128]
    const float* b1 = (const float*)d_in[3];   // [128]
    const float* W2 = (const float*)d_in[4];   // [128, 64]
    const float* b2 = (const float*)d_in[5];   // [64]
    float* out = (float*)d_out;                // [N, 64]

    const int N = in_sizes[0] / DIN;
    const int E = in_sizes[1] / 2;
    const int* src = ei;
    const int* dst = ei + E;

    int *cnt, *off, *cur, *esrc;
    float *dinv, *a2;
    __half *h1s, *h2s;
    cudaGetSymbolAddress((void**)&cnt,  g_cnt);
    cudaGetSymbolAddress((void**)&off,  g_off);
    cudaGetSymbolAddress((void**)&cur,  g_cur);
    cudaGetSymbolAddress((void**)&esrc, g_esrc);
    cudaGetSymbolAddress((void**)&dinv, g_dinv);
    cudaGetSymbolAddress((void**)&h1s,  g_h1s);
    cudaGetSymbolAddress((void**)&a2,   g_a2);
    cudaGetSymbolAddress((void**)&h2s,  g_h2s);

    const int T = 256;

    // CSR build + normalization
    k_zero<<<(N + T - 1) / T, T>>>(cnt, N);
    k_hist<<<(E + T - 1) / T, T>>>(dst, cnt, E);
    k_scan<<<1, 1024>>>(cnt, off, cur, N);
    k_dinv<<<(N + T - 1) / T, T>>>(cnt, dinv, N);
    k_scatter<<<(E + T - 1) / T, T>>>(src, dst, cur, esrc, E);

    dim3 blk(16, 16);
    // layer 1
    k_gemm1<<<(N + 127) / 128, blk>>>(x, W1, dinv, h1s, N);
    k_agg1<<<(N * 32 + T - 1) / T, T>>>(off, esrc, dinv, h1s, b1, a2, N);
    // layer 2
    k_gemm2<<<(N + 127) / 128, blk>>>(a2, W2, dinv, h2s, N);
    k_agg2<<<(N * 32 + T - 1) / T, T>>>(off, esrc, dinv, h2s, b2, out, N);
}

// round 4
// speedup vs baseline: 3.6308x; 2.4746x over previous
#include <cuda_runtime.h>
#include <cuda_fp16.h>
#include <mma.h>
#include <cstdint>

using namespace nvcuda;

#define MAXN 100000
#define MAXE 1600000
#define DIN 128
#define DH  128
#define DOUT 64

// ---------------- scratch (device globals; no allocation allowed) ----------
__device__ int    g_cnt [MAXN];
__device__ int    g_off [MAXN];
__device__ int    g_cur [MAXN];
__device__ int    g_esrc[MAXE];
__device__ int    g_total;
__device__ float  g_dinv[MAXN];
__device__ __half g_h1s [(size_t)MAXN * DH];    // (x@W1) * dinv[row], fp16
__device__ __half g_a2  [(size_t)MAXN * DH];    // relu(agg1 + b1), fp16
__device__ __half g_h2s [(size_t)MAXN * DOUT];  // (a2@W2) * dinv[row], fp16

struct alignas(8) H2x2 { __half2 a, b; };

// ---------------------------------------------------------------------------
// CSR build
// ---------------------------------------------------------------------------
__global__ void k_zero(int* c, int n) {
    int i = blockIdx.x * blockDim.x + threadIdx.x;
    if (i < n) c[i] = 0;
    if (i == 0) g_total = 0;
}

__global__ void k_hist(const int* __restrict__ dst, int* cnt, int ne) {
    int i = blockIdx.x * blockDim.x + threadIdx.x;
    if (i < ne) atomicAdd(&cnt[dst[i]], 1);
}

// Per-block scan + atomic base allocation (segment placement is arbitrary but
// segment contents per node are fixed). Also computes dinv.
__global__ void k_offsets(const int* __restrict__ cnt, int* __restrict__ off,
                          int* __restrict__ cur, float* __restrict__ dinv, int n) {
    __shared__ int s[256];
    __shared__ int base;
    int i = blockIdx.x * 256 + threadIdx.x;
    int c = (i < n) ? cnt[i] : 0;
    s[threadIdx.x] = c;
    __syncthreads();
#pragma unroll
    for (int d = 1; d < 256; d <<= 1) {
        int v = (threadIdx.x >= d) ? s[threadIdx.x - d] : 0;
        __syncthreads();
        s[threadIdx.x] += v;
        __syncthreads();
    }
    if (threadIdx.x == 255) base = atomicAdd(&g_total, s[255]);
    __syncthreads();
    if (i < n) {
        int o = base + s[threadIdx.x] - c;
        off[i] = o;
        cur[i] = o;
        dinv[i] = rsqrtf((float)c + 1.0f);
    }
}

__global__ void k_scatter(const int* __restrict__ src, const int* __restrict__ dst,
                          int* cur, int* __restrict__ esrc, int ne) {
    int i = blockIdx.x * blockDim.x + threadIdx.x;
    if (i < ne) {
        int pos = atomicAdd(&cur[dst[i]], 1);
        esrc[pos] = src[i];
    }
}

// ---------------------------------------------------------------------------
// GEMM1 (wmma fp16, fp32 accum): h1s[m,:] = fp16( (x @ W1)[m,:] * dinv[m] )
// Block tile 128x128, 8 warps (4m x 2n), warp tile 32x64, BK=32.
// ---------------------------------------------------------------------------
__global__ __launch_bounds__(256)
void k_gemm1(const float* __restrict__ A, const float* __restrict__ W,
             const float* __restrict__ dinv, __half* __restrict__ C, int M) {
    __shared__ __align__(16) __half Ah[128][40];   // 10240 B
    __shared__ __align__(16) __half Wh[32][136];   //  8704 B
    __shared__ __align__(16) float  scr[8][16 * 20]; // 10240 B

    const int tid = threadIdx.x;
    const int wid = tid >> 5, lane = tid & 31;
    const int m0 = blockIdx.x * 128;
    const int wm = wid & 3, wn = wid >> 2;

    wmma::fragment<wmma::accumulator, 16, 16, 16, float> acc[2][4];
#pragma unroll
    for (int i = 0; i < 2; i++)
#pragma unroll
        for (int j = 0; j < 4; j++) wmma::fill_fragment(acc[i][j], 0.0f);

    for (int k0 = 0; k0 < 128; k0 += 32) {
        // A chunk 128x32 fp32 -> fp16 smem (1024 float4, 4/thread)
#pragma unroll
        for (int i = 0; i < 4; i++) {
            int idx = i * 256 + tid;
            int r = idx >> 3, c4 = idx & 7;
            float4 v = make_float4(0.f, 0.f, 0.f, 0.f);
            if (m0 + r < M) v = *(const float4*)(A + (size_t)(m0 + r) * 128 + k0 + c4 * 4);
            *(__half2*)&Ah[r][c4 * 4]     = __floats2half2_rn(v.x, v.y);
            *(__half2*)&Ah[r][c4 * 4 + 2] = __floats2half2_rn(v.z, v.w);
        }
        // W chunk 32x128 fp32 -> fp16 smem
#pragma unroll
        for (int i = 0; i < 4; i++) {
            int idx = i * 256 + tid;
            int r = idx >> 5, c4 = idx & 31;
            float4 v = *(const float4*)(W + (size_t)(k0 + r) * 128 + c4 * 4);
            *(__half2*)&Wh[r][c4 * 4]     = __floats2half2_rn(v.x, v.y);
            *(__half2*)&Wh[r][c4 * 4 + 2] = __floats2half2_rn(v.z, v.w);
        }
        __syncthreads();
#pragma unroll
        for (int kk = 0; kk < 32; kk += 16) {
            wmma::fragment<wmma::matrix_a, 16, 16, 16, __half, wmma::row_major> af[2];
#pragma unroll
            for (int mi = 0; mi < 2; mi++)
                wmma::load_matrix_sync(af[mi], &Ah[wm * 32 + mi * 16][kk], 40);
#pragma unroll
            for (int ni = 0; ni < 4; ni++) {
                wmma::fragment<wmma::matrix_b, 16, 16, 16, __half, wmma::row_major> bf;
                wmma::load_matrix_sync(bf, &Wh[kk][wn * 64 + ni * 16], 136);
#pragma unroll
                for (int mi = 0; mi < 2; mi++)
                    wmma::mma_sync(acc[mi][ni], af[mi], bf, acc[mi][ni]);
            }
        }
        __syncthreads();
    }

    // epilogue: scale by dinv[row], convert fp16
#pragma unroll
    for (int mi = 0; mi < 2; mi++)
#pragma unroll
        for (int ni = 0; ni < 4; ni++) {
            wmma::store_matrix_sync(&scr[wid][0], acc[mi][ni], 20, wmma::mem_row_major);
            __syncwarp();
            int r = lane >> 1, h = lane & 1;
            int gm = m0 + wm * 32 + mi * 16 + r;
            if (gm < M) {
                float s = dinv[gm];
                const float* p = &scr[wid][r * 20 + h * 8];
                __half2 o[4];
#pragma unroll
                for (int j = 0; j < 4; j++)
                    o[j] = __floats2half2_rn(p[2 * j] * s, p[2 * j + 1] * s);
                *(uint4*)(C + (size_t)gm * 128 + wn * 64 + ni * 16 + h * 8) = *(uint4*)o;
            }
            __syncwarp();
        }
}

// ---------------------------------------------------------------------------
// GEMM2 (wmma): h2s[m,:] = fp16( (a2 @ W2)[m,:] * dinv[m] ), a2 already fp16
// Block tile 128x64, 8 warps (4m x 2n), warp tile 32x32, BK=32.
// ---------------------------------------------------------------------------
__global__ __launch_bounds__(256)
void k_gemm2(const __half* __restrict__ A, const float* __restrict__ W,
             const float* __restrict__ dinv, __half* __restrict__ C, int M) {
    __shared__ __align__(16) __half Ah[128][40];
    __shared__ __align__(16) __half Wh[32][72];
    __shared__ __align__(16) float  scr[8][16 * 20];

    const int tid = threadIdx.x;
    const int wid = tid >> 5, lane = tid & 31;
    const int m0 = blockIdx.x * 128;
    const int wm = wid & 3, wn = wid >> 2;

    wmma::fragment<wmma::accumulator, 16, 16, 16, float> acc[2][2];
#pragma unroll
    for (int i = 0; i < 2; i++)
#pragma unroll
        for (int j = 0; j < 2; j++) wmma::fill_fragment(acc[i][j], 0.0f);

    for (int k0 = 0; k0 < 128; k0 += 32) {
        // A chunk 128x32 fp16 (512 uint4, 2/thread)
#pragma unroll
        for (int i = 0; i < 2; i++) {
            int idx = i * 256 + tid;
            int r = idx >> 2, c8 = idx & 3;
            uint4 v = make_uint4(0, 0, 0, 0);
            if (m0 + r < M) v = *(const uint4*)(A + (size_t)(m0 + r) * 128 + k0 + c8 * 8);
            *(uint4*)&Ah[r][c8 * 8] = v;
        }
        // W chunk 32x64 fp32 -> fp16 (512 float4, 2/thread)
#pragma unroll
        for (int i = 0; i < 2; i++) {
            int idx = i * 256 + tid;
            int r = idx >> 4, c4 = idx & 15;
            float4 v = *(const float4*)(W + (size_t)(k0 + r) * 64 + c4 * 4);
            *(__half2*)&Wh[r][c4 * 4]     = __floats2half2_rn(v.x, v.y);
            *(__half2*)&Wh[r][c4 * 4 + 2] = __floats2half2_rn(v.z, v.w);
        }
        __syncthreads();
#pragma unroll
        for (int kk = 0; kk < 32; kk += 16) {
            wmma::fragment<wmma::matrix_a, 16, 16, 16, __half, wmma::row_major> af[2];
#pragma unroll
            for (int mi = 0; mi < 2; mi++)
                wmma::load_matrix_sync(af[mi], &Ah[wm * 32 + mi * 16][kk], 40);
#pragma unroll
            for (int ni = 0; ni < 2; ni++) {
                wmma::fragment<wmma::matrix_b, 16, 16, 16, __half, wmma::row_major> bf;
                wmma::load_matrix_sync(bf, &Wh[kk][wn * 32 + ni * 16], 72);
#pragma unroll
                for (int mi = 0; mi < 2; mi++)
                    wmma::mma_sync(acc[mi][ni], af[mi], bf, acc[mi][ni]);
            }
        }
        __syncthreads();
    }

#pragma unroll
    for (int mi = 0; mi < 2; mi++)
#pragma unroll
        for (int ni = 0; ni < 2; ni++) {
            wmma::store_matrix_sync(&scr[wid][0], acc[mi][ni], 20, wmma::mem_row_major);
            __syncwarp();
            int r = lane >> 1, h = lane & 1;
            int gm = m0 + wm * 32 + mi * 16 + r;
            if (gm < M) {
                float s = dinv[gm];
                const float* p = &scr[wid][r * 20 + h * 8];
                __half2 o[4];
#pragma unroll
                for (int j = 0; j < 4; j++)
                    o[j] = __floats2half2_rn(p[2 * j] * s, p[2 * j + 1] * s);
                *(uint4*)(C + (size_t)gm * 64 + wn * 32 + ni * 16 + h * 8) = *(uint4*)o;
            }
            __syncwarp();
        }
}

// ---------------------------------------------------------------------------
// Aggregation layer 1: one warp per node, D=128.
// a2[n] = fp16( relu( dinv[n] * (sum_{src} h1s[src] + h1s[n]) + b1 ) )
// ---------------------------------------------------------------------------
__global__ void k_agg1(const int* __restrict__ off, const int* __restrict__ cnt,
                       const int* __restrict__ esrc,
                       const float* __restrict__ dinv, const __half* __restrict__ h1s,
                       const float* __restrict__ b1, __half* __restrict__ a2, int n) {
    int node = (blockIdx.x * blockDim.x + threadIdx.x) >> 5;
    int lane = threadIdx.x & 31;
    if (node >= n) return;

    const H2x2* rows = (const H2x2*)h1s;  // 32 H2x2 per row

    H2x2 r = rows[(size_t)node * 32 + lane];  // self (pre-scaled by dinv)
    float2 f0 = __half22float2(r.a), f1 = __half22float2(r.b);
    float4 acc = make_float4(f0.x, f0.y, f1.x, f1.y);

    int e = off[node];
    const int end = e + cnt[node];
    for (; e + 3 < end; e += 4) {
        int s0 = esrc[e], s1 = esrc[e + 1], s2 = esrc[e + 2], s3 = esrc[e + 3];
        H2x2 r0 = rows[(size_t)s0 * 32 + lane];
        H2x2 r1 = rows[(size_t)s1 * 32 + lane];
        H2x2 r2 = rows[(size_t)s2 * 32 + lane];
        H2x2 r3 = rows[(size_t)s3 * 32 + lane];
        float2 a0 = __half22float2(r0.a), a1 = __half22float2(r0.b);
        float2 c0 = __half22float2(r1.a), c1 = __half22float2(r1.b);
        float2 d0 = __half22float2(r2.a), d1 = __half22float2(r2.b);
        float2 e0 = __half22float2(r3.a), e1 = __half22float2(r3.b);
        acc.x += (a0.x + c0.x) + (d0.x + e0.x);
        acc.y += (a0.y + c0.y) + (d0.y + e0.y);
        acc.z += (a1.x + c1.x) + (d1.x + e1.x);
        acc.w += (a1.y + c1.y) + (d1.y + e1.y);
    }
    for (; e < end; e++) {
        H2x2 r0 = rows[(size_t)esrc[e] * 32 + lane];
        float2 a0 = __half22float2(r0.a), a1 = __half22float2(r0.b);
        acc.x += a0.x; acc.y += a0.y; acc.z += a1.x; acc.w += a1.y;
    }

    float w = dinv[node];
    float4 bb = ((const float4*)b1)[lane];
    float ox = fmaxf(acc.x * w + bb.x, 0.0f);
    float oy = fmaxf(acc.y * w + bb.y, 0.0f);
    float oz = fmaxf(acc.z * w + bb.z, 0.0f);
    float ow = fmaxf(acc.w * w + bb.w, 0.0f);
    H2x2 o;
    o.a = __floats2half2_rn(ox, oy);
    o.b = __floats2half2_rn(oz, ow);
    ((H2x2*)a2)[(size_t)node * 32 + lane] = o;
}

// ---------------------------------------------------------------------------
// Aggregation layer 2: one warp per node, D=64. out = dinv*(sum+self) + b2
// ---------------------------------------------------------------------------
__global__ void k_agg2(const int* __restrict__ off, const int* __restrict__ cnt,
                       const int* __restrict__ esrc,
                       const float* __restrict__ dinv, const __half* __restrict__ h2s,
                       const float* __restrict__ b2, float* __restrict__ out, int n) {
    int node = (blockIdx.x * blockDim.x + threadIdx.x) >> 5;
    int lane = threadIdx.x & 31;
    if (node >= n) return;

    const __half2* rows = (const __half2*)h2s;  // 32 half2 per row

    float2 acc = __half22float2(rows[(size_t)node * 32 + lane]);  // self

    int e = off[node];
    const int end = e + cnt[node];
    for (; e + 3 < end; e += 4) {
        int s0 = esrc[e], s1 = esrc[e + 1], s2 = esrc[e + 2], s3 = esrc[e + 3];
        float2 a = __half22float2(rows[(size_t)s0 * 32 + lane]);
        float2 b = __half22float2(rows[(size_t)s1 * 32 + lane]);
        float2 c = __half22float2(rows[(size_t)s2 * 32 + lane]);
        float2 d = __half22float2(rows[(size_t)s3 * 32 + lane]);
        acc.x += (a.x + b.x) + (c.x + d.x);
        acc.y += (a.y + b.y) + (c.y + d.y);
    }
    for (; e < end; e++) {
        float2 a = __half22float2(rows[(size_t)esrc[e] * 32 + lane]);
        acc.x += a.x; acc.y += a.y;
    }

    float w = dinv[node];
    float2 bb = ((const float2*)b2)[lane];
    float2 o;
    o.x = acc.x * w + bb.x;
    o.y = acc.y * w + bb.y;
    ((float2*)out)[(size_t)node * 32 + lane] = o;
}

// ---------------------------------------------------------------------------
// Launch
// ---------------------------------------------------------------------------
extern "C" void kernel_launch(void* const* d_in, const int* in_sizes, int n_in,
                              void* d_out, int out_size) {
    const float* x  = (const float*)d_in[0];   // [N, 128]
    const int*   ei = (const int*)  d_in[1];   // [2, E]
    const float* W1 = (const float*)d_in[2];   // [128, 128]
    const float* b1 = (const float*)d_in[3];   // [128]
    const float* W2 = (const float*)d_in[4];   // [128, 64]
    const float* b2 = (const float*)d_in[5];   // [64]
    float* out = (float*)d_out;                // [N, 64]

    const int N = in_sizes[0] / DIN;
    const int E = in_sizes[1] / 2;
    const int* src = ei;
    const int* dst = ei + E;

    int *cnt, *off, *cur, *esrc;
    float *dinv;
    __half *h1s, *a2, *h2s;
    cudaGetSymbolAddress((void**)&cnt,  g_cnt);
    cudaGetSymbolAddress((void**)&off,  g_off);
    cudaGetSymbolAddress((void**)&cur,  g_cur);
    cudaGetSymbolAddress((void**)&esrc, g_esrc);
    cudaGetSymbolAddress((void**)&dinv, g_dinv);
    cudaGetSymbolAddress((void**)&h1s,  g_h1s);
    cudaGetSymbolAddress((void**)&a2,   g_a2);
    cudaGetSymbolAddress((void**)&h2s,  g_h2s);

    const int T = 256;

    // CSR build + normalization
    k_zero<<<(N + T - 1) / T, T>>>(cnt, N);
    k_hist<<<(E + T - 1) / T, T>>>(dst, cnt, E);
    k_offsets<<<(N + 255) / 256, 256>>>(cnt, off, cur, dinv, N);
    k_scatter<<<(E + T - 1) / T, T>>>(src, dst, cur, esrc, E);

    // layer 1
    k_gemm1<<<(N + 127) / 128, 256>>>(x, W1, dinv, h1s, N);
    k_agg1<<<(N * 32 + T - 1) / T, T>>>(off, cnt, esrc, dinv, h1s, b1, a2, N);
    // layer 2
    k_gemm2<<<(N + 127) / 128, 256>>>(a2, W2, dinv, h2s, N);
    k_agg2<<<(N * 32 + T - 1) / T, T>>>(off, cnt, esrc, dinv, h2s, b2, out, N);
}